// round 10
// baseline (speedup 1.0000x reference)
#include <cuda_runtime.h>
#include <cstdint>

#define F 128
#define NT 4
#define MAXN 50000
#define MAXE 800000
#define NSEG (NT * MAXN)
#define KP_TOT 320                 // (NT+1)*F/2 k-pairs

// ---- scratch (__device__ globals; allocation-free rule) -------------------
// A operand bf16x2 planes, layout [row][320 kpairs]:
//   kpairs [0,64)   = x row
//   kpairs [64+64t) = mean over type-t in-neighbors
__device__ __align__(128) uint32_t g_ah[(size_t)MAXN * KP_TOT];
__device__ __align__(128) uint32_t g_al[(size_t)MAXN * KP_TOT];
__device__ __align__(128) int   g_hist[NSEG + 1];
__device__ __align__(128) int   g_segstart[NSEG + 1];
__device__ __align__(128) int   g_cursor[NSEG];
__device__ __align__(128) int   g_srcs[MAXE];
__device__ __align__(128) int   g_bsum[1024];
__device__ __align__(128) int   g_boff[1024];
__device__ __align__(128) float g_wcat[(NT + 1) * F * F];        // [640][128]
__device__ __align__(128) uint32_t g_wb_h[KP_TOT * F];           // [kpair][n]
__device__ __align__(128) uint32_t g_wb_l[KP_TOT * F];
__device__ __align__(128) float g_bavg[F];

// ---- bf16 helpers ---------------------------------------------------------
__device__ __forceinline__ uint32_t pack_bf16x2(float flo, float fhi) {
    uint32_t r;
    asm("cvt.rn.bf16x2.f32 %0, %1, %2;" : "=r"(r) : "f"(fhi), "f"(flo));
    return r;
}
__device__ __forceinline__ float bf16_round(float f) {
    uint32_t u;
    asm("cvt.rn.bf16x2.f32 %0, %1, %2;" : "=r"(u) : "f"(0.f), "f"(f));
    return __uint_as_float(u << 16);
}
__device__ __forceinline__ void mma_bf16(float* c, const uint32_t* a,
                                         uint32_t b0, uint32_t b1) {
    asm volatile(
        "mma.sync.aligned.m16n8k16.row.col.f32.bf16.bf16.f32 "
        "{%0,%1,%2,%3}, {%4,%5,%6,%7}, {%8,%9}, {%0,%1,%2,%3};"
        : "+f"(c[0]), "+f"(c[1]), "+f"(c[2]), "+f"(c[3])
        : "r"(a[0]), "r"(a[1]), "r"(a[2]), "r"(a[3]), "r"(b0), "r"(b1));
}
__device__ __forceinline__ void cp16(void* smem, const void* gmem) {
    uint32_t s = (uint32_t)__cvta_generic_to_shared(smem);
    asm volatile("cp.async.cg.shared.global [%0], [%1], 16;"
                 :: "r"(s), "l"(gmem));
}

// ---------------------------------------------------------------------------
// W prep
// ---------------------------------------------------------------------------
__global__ void prep_w_kernel(const float* __restrict__ Wself,
                              const float* __restrict__ Wneigh,
                              const float* __restrict__ b) {
    int idx = blockIdx.x * blockDim.x + threadIdx.x;
    if (idx < F * F) {
        float s = 0.f;
        #pragma unroll
        for (int t = 0; t < NT; t++) s += Wself[t * F * F + idx];
        g_wcat[idx] = 0.25f * s;
        #pragma unroll
        for (int t = 0; t < NT; t++)
            g_wcat[(1 + t) * F * F + idx] = 0.25f * Wneigh[t * F * F + idx];
    }
    if (idx < F) {
        float s = 0.f;
        #pragma unroll
        for (int t = 0; t < NT; t++) s += b[t * F + idx];
        g_bavg[idx] = 0.25f * s;
    }
}

__global__ void prep_wb_kernel() {
    int idx = blockIdx.x * blockDim.x + threadIdx.x;   // over 320*128
    if (idx >= KP_TOT * F) return;
    int kp = idx >> 7;
    int n  = idx & 127;
    float f0 = g_wcat[(2 * kp) * F + n];
    float f1 = g_wcat[(2 * kp + 1) * F + n];
    g_wb_h[idx] = pack_bf16x2(f0, f1);
    g_wb_l[idx] = pack_bf16x2(f0 - bf16_round(f0), f1 - bf16_round(f1));
}

// x -> plane kpairs [0,64)
__global__ void prep_xplanes_kernel(const float* __restrict__ x, int N) {
    int idx = blockIdx.x * blockDim.x + threadIdx.x;   // over N*64
    if (idx >= N * 64) return;
    int row = idx >> 6;
    int kp  = idx & 63;
    float2 v = *reinterpret_cast<const float2*>(x + (size_t)row * F + kp * 2);
    size_t o = (size_t)row * KP_TOT + kp;
    g_ah[o] = pack_bf16x2(v.x, v.y);
    g_al[o] = pack_bf16x2(v.x - bf16_round(v.x), v.y - bf16_round(v.y));
}

// ---------------------------------------------------------------------------
// Counting sort by (dst,type); seg id = (d << 2) | t
// ---------------------------------------------------------------------------
__global__ void zero_hist_kernel(int S) {
    int i = blockIdx.x * blockDim.x + threadIdx.x;
    if (i <= S) g_hist[i] = 0;
}

__global__ void hist_kernel(const int* __restrict__ ei,
                            const int* __restrict__ et, int E, int N) {
    int e = blockIdx.x * blockDim.x + threadIdx.x;
    if (e >= E) return;
    int s = __ldg(ei + e);
    int d = __ldg(ei + E + e);
    int t = __ldg(et + e) & 3;
    if ((unsigned)s >= (unsigned)N || (unsigned)d >= (unsigned)N) return;
    atomicAdd(&g_hist[(d << 2) | t], 1);
}

__global__ void scan_a_kernel(int S) {
    __shared__ int sm[256];
    int lt = threadIdx.x;
    int i = blockIdx.x * 256 + lt;
    int h = (i < S) ? g_hist[i] : 0;
    sm[lt] = h;
    __syncthreads();
    #pragma unroll
    for (int d = 1; d < 256; d <<= 1) {
        int v = (lt >= d) ? sm[lt - d] : 0;
        __syncthreads();
        sm[lt] += v;
        __syncthreads();
    }
    if (i < S) g_segstart[i] = sm[lt] - h;
    if (lt == 255) g_bsum[blockIdx.x] = sm[255];
}

__global__ void scan_b_kernel(int nb) {
    __shared__ int sm[1024];
    int lt = threadIdx.x;
    int v = (lt < nb) ? g_bsum[lt] : 0;
    sm[lt] = v;
    __syncthreads();
    #pragma unroll
    for (int d = 1; d < 1024; d <<= 1) {
        int u = (lt >= d) ? sm[lt - d] : 0;
        __syncthreads();
        sm[lt] += u;
        __syncthreads();
    }
    if (lt < nb) g_boff[lt] = sm[lt] - v;
}

__global__ void scan_c_kernel(int S, int E) {
    int i = blockIdx.x * 256 + threadIdx.x;
    if (i < S) {
        int v = g_segstart[i] + g_boff[blockIdx.x];
        g_segstart[i] = v;
        g_cursor[i] = v;
    }
    if (i == 0) g_segstart[S] = E;
}

__global__ void reorder_kernel(const int* __restrict__ ei,
                               const int* __restrict__ et, int E, int N) {
    int e = blockIdx.x * blockDim.x + threadIdx.x;
    if (e >= E) return;
    int s = __ldg(ei + e);
    int d = __ldg(ei + E + e);
    int t = __ldg(et + e) & 3;
    if ((unsigned)s >= (unsigned)N || (unsigned)d >= (unsigned)N) return;
    int pos = atomicAdd(&g_cursor[(d << 2) | t], 1);
    g_srcs[pos] = s;
}

// one warp per segment: gather x rows, mean, write bf16 hi/lo planes
__global__ __launch_bounds__(256) void gather_mean_kernel(
        const float* __restrict__ x, int N) {
    int warp = (blockIdx.x * blockDim.x + threadIdx.x) >> 5;
    int lane = threadIdx.x & 31;
    int S = N << 2;
    if (warp >= S) return;
    int t = warp & 3;
    int d = warp >> 2;
    int p0 = g_segstart[warp];
    int p1 = g_segstart[warp + 1];
    float4 acc = make_float4(0.f, 0.f, 0.f, 0.f);
    for (int p = p0; p < p1; p++) {
        int src = g_srcs[p];
        float4 v = __ldg(reinterpret_cast<const float4*>(x + (size_t)src * F) + lane);
        acc.x += v.x; acc.y += v.y; acc.z += v.z; acc.w += v.w;
    }
    float inv = (p1 > p0) ? 1.0f / (float)(p1 - p0) : 0.0f;
    acc.x *= inv; acc.y *= inv; acc.z *= inv; acc.w *= inv;
    size_t base = (size_t)d * KP_TOT + 64 + (t << 6) + (lane << 1);
    uint2 hv, lv;
    hv.x = pack_bf16x2(acc.x, acc.y);
    hv.y = pack_bf16x2(acc.z, acc.w);
    lv.x = pack_bf16x2(acc.x - bf16_round(acc.x), acc.y - bf16_round(acc.y));
    lv.y = pack_bf16x2(acc.z - bf16_round(acc.z), acc.w - bf16_round(acc.w));
    *reinterpret_cast<uint2*>(g_ah + base) = hv;
    *reinterpret_cast<uint2*>(g_al + base) = lv;
}

// ---------------------------------------------------------------------------
// GEMM: out[N,128] = Aplanes[N,320kp] @ Wplanes + b_avg
// 3-term bf16 emulation; BM=128, BN=128; 8 kpairs/tile; 2-stage cp.async
// smem: A 2*128*12*4*2 = 24.6KB, B 2*8*132*4*2 = 16.9KB  -> 41.5KB < 48KB
// ---------------------------------------------------------------------------
#define BM 128
#define BN 128
#define STAGES 2
#define ALD 12     // u32 per A row (8 used); 48B rows, 16B-aligned, conflict-free
#define BLD 132    // u32 per B row (128 used); 528B rows, 16B-aligned, <=2-way

__global__ __launch_bounds__(256, 2) void gemm_kernel(float* __restrict__ out,
                                                      int N) {
    __shared__ uint32_t As_h[STAGES][BM][ALD];
    __shared__ uint32_t As_l[STAGES][BM][ALD];
    __shared__ uint32_t Bs_h[STAGES][8][BLD];
    __shared__ uint32_t Bs_l[STAGES][8][BLD];

    int tid  = threadIdx.x;
    int lane = tid & 31;
    int w    = tid >> 5;
    int warpM = w & 3;
    int warpN = w >> 2;
    int g  = lane >> 2;
    int tq = lane & 3;
    int m0 = blockIdx.x * BM;

    const int T = KP_TOT / 8;            // 40 tiles

    float acc[2][8][4];
    #pragma unroll
    for (int mi = 0; mi < 2; mi++)
        #pragma unroll
        for (int ni = 0; ni < 8; ni++)
            #pragma unroll
            for (int j = 0; j < 4; j++) acc[mi][ni][j] = 0.f;

    // per-thread load coords (constant across tiles)
    int rowl = tid >> 1;                 // 0..127
    int ch   = tid & 1;                  // which 16B chunk of the 8-kpair window
    int grow = m0 + rowl; if (grow >= N) grow = N - 1;
    const uint32_t* gAh = g_ah + (size_t)grow * KP_TOT + ch * 4;
    const uint32_t* gAl = g_al + (size_t)grow * KP_TOT + ch * 4;
    int bkp = tid >> 5;                  // 0..7
    int bn4 = lane << 2;                 // 0..124

    #define ISSUE_TILE(stage, tile)                                            \
    do {                                                                       \
        int tt = (tile) < T ? (tile) : T - 1;                                  \
        int kc2 = tt * 8;                                                      \
        cp16(&As_h[stage][rowl][ch * 4], gAh + kc2);                           \
        cp16(&As_l[stage][rowl][ch * 4], gAl + kc2);                           \
        cp16(&Bs_h[stage][bkp][bn4], g_wb_h + (kc2 + bkp) * F + bn4);          \
        cp16(&Bs_l[stage][bkp][bn4], g_wb_l + (kc2 + bkp) * F + bn4);          \
        asm volatile("cp.async.commit_group;" ::: "memory");                   \
    } while (0)

    ISSUE_TILE(0, 0);

    for (int t = 0; t < T; t++) {
        ISSUE_TILE((t + 1) & 1, t + 1);
        asm volatile("cp.async.wait_group 1;" ::: "memory");
        __syncthreads();

        int buf = t & 1;
        uint32_t ah[2][4], al[2][4];
        #pragma unroll
        for (int mi = 0; mi < 2; mi++) {
            int mrow = warpM * 32 + mi * 16 + g;
            ah[mi][0] = As_h[buf][mrow][tq];
            ah[mi][1] = As_h[buf][mrow + 8][tq];
            ah[mi][2] = As_h[buf][mrow][tq + 4];
            ah[mi][3] = As_h[buf][mrow + 8][tq + 4];
            al[mi][0] = As_l[buf][mrow][tq];
            al[mi][1] = As_l[buf][mrow + 8][tq];
            al[mi][2] = As_l[buf][mrow][tq + 4];
            al[mi][3] = As_l[buf][mrow + 8][tq + 4];
        }
        #pragma unroll
        for (int ni = 0; ni < 8; ni++) {
            int ncol = warpN * 64 + ni * 8 + g;
            uint32_t bh0 = Bs_h[buf][tq][ncol];
            uint32_t bh1 = Bs_h[buf][tq + 4][ncol];
            uint32_t bl0 = Bs_l[buf][tq][ncol];
            uint32_t bl1 = Bs_l[buf][tq + 4][ncol];
            #pragma unroll
            for (int mi = 0; mi < 2; mi++) {
                mma_bf16(acc[mi][ni], ah[mi], bh0, bh1);
                mma_bf16(acc[mi][ni], ah[mi], bl0, bl1);
                mma_bf16(acc[mi][ni], al[mi], bh0, bh1);
            }
        }
        __syncthreads();
    }
    #undef ISSUE_TILE

    #pragma unroll
    for (int ni = 0; ni < 8; ni++) {
        int c0 = warpN * 64 + ni * 8 + 2 * tq;
        float b0 = g_bavg[c0];
        float b1 = g_bavg[c0 + 1];
        #pragma unroll
        for (int mi = 0; mi < 2; mi++) {
            int r0 = m0 + warpM * 32 + mi * 16 + g;
            if (r0 < N) {
                float2 v = make_float2(acc[mi][ni][0] + b0, acc[mi][ni][1] + b1);
                *reinterpret_cast<float2*>(out + (size_t)r0 * F + c0) = v;
            }
            int r1 = r0 + 8;
            if (r1 < N) {
                float2 v = make_float2(acc[mi][ni][2] + b0, acc[mi][ni][3] + b1);
                *reinterpret_cast<float2*>(out + (size_t)r1 * F + c0) = v;
            }
        }
    }
}

// ---------------------------------------------------------------------------
extern "C" void kernel_launch(void* const* d_in, const int* in_sizes, int n_in,
                              void* d_out, int out_size) {
    const float* x      = (const float*)d_in[0];
    const int*   ei     = (const int*)d_in[1];
    const int*   et     = (const int*)d_in[2];
    const float* Wself  = (const float*)d_in[3];
    const float* Wneigh = (const float*)d_in[4];
    const float* b      = (const float*)d_in[5];
    float*       out    = (float*)d_out;

    int N = in_sizes[0] / F;
    int E = in_sizes[2];
    if (N > MAXN || E > MAXE) return;

    int S = N << 2;
    int scanBlocks = (S + 255) / 256;
    if (scanBlocks > 1024) return;

    prep_w_kernel<<<(F * F + 255) / 256, 256>>>(Wself, Wneigh, b);
    prep_wb_kernel<<<(KP_TOT * F + 255) / 256, 256>>>();
    prep_xplanes_kernel<<<(N * 64 + 255) / 256, 256>>>(x, N);

    zero_hist_kernel<<<(S + 256) / 256, 256>>>(S);
    hist_kernel<<<(E + 255) / 256, 256>>>(ei, et, E, N);
    scan_a_kernel<<<scanBlocks, 256>>>(S);
    scan_b_kernel<<<1, 1024>>>(scanBlocks);
    scan_c_kernel<<<scanBlocks, 256>>>(S, E);
    reorder_kernel<<<(E + 255) / 256, 256>>>(ei, et, E, N);
    gather_mean_kernel<<<(S * 32 + 255) / 256, 256>>>(x, N);

    gemm_kernel<<<(N + BM - 1) / BM, 256>>>(out, N);
}